// round 16
// baseline (speedup 1.0000x reference)
#include <cuda_runtime.h>

#define N_ROWS   1000000
#define D        64
#define INNER    16
#define NTRI     136            // 16*17/2
#define NOUT     152            // NTRI + INNER
#define HALF     76             // outputs per half (38 u64 = 19 ulonglong2)
#define NSEG     100000
#define OUTD     64
#define TPB      128
#define KSPLIT   32             // k-rows [0,32) from smem, [32,64) from constant

typedef unsigned long long ull;

// Per-segment scratch: [0:16) = t accumulation, [16:152) = F lower-triangle accumulation
__device__ __align__(16) float g_scratch[(size_t)NSEG * NOUT];

// W rows k=32..63 (32 x 152 floats = 19456 B) in constant memory -> LDC port,
// bypassing the smem crossbar that profiling showed as the binding pipe (L1 70.8%).
__constant__ ulonglong2 cW2[(KSPLIT * NOUT) / 4];   // 1216 ulonglong2

__device__ __forceinline__ ull ffma2(ull a, ull b, ull c) {
    ull d;
    asm("fma.rn.f32x2 %0, %1, %2, %3;" : "=l"(d) : "l"(a), "l"(b), "l"(c));
    return d;
}

__device__ __forceinline__ void red_v4(float* p, float a, float b, float c, float d) {
    asm volatile("red.global.add.v4.f32 [%0], {%1, %2, %3, %4};"
                 :: "l"(p), "f"(a), "f"(b), "f"(c), "f"(d) : "memory");
}

__device__ __forceinline__ constexpr int TRI(int i, int j) { return i * (i + 1) / 2 + j; }

// fast tanh: 1 - 2/(exp(2x)+1).  2 MUFU + few ALU, ~1e-6 abs err.
__device__ __forceinline__ float fast_tanh(float x) {
    float e = __expf(2.0f * x);
    return 1.0f - __fdividef(2.0f, e + 1.0f);
}

// ---------------------------------------------------------------------------
// Kernel 0: zero the segment scratch
// ---------------------------------------------------------------------------
__global__ void zero_kernel() {
    size_t i = (size_t)blockIdx.x * blockDim.x + threadIdx.x;
    const size_t n4 = (size_t)NSEG * NOUT / 4;
    if (i < n4) {
        ((float4*)g_scratch)[i] = make_float4(0.f, 0.f, 0.f, 0.f);
    }
}

// No-op: pads launch count to 6 so ncu's capture slot stays on main_kernel (pos 3).
__global__ void noop_kernel() {}

// ---------------------------------------------------------------------------
// Kernel 1: 2-row register-blocked GEMM (round-12 winner) with DUAL-PORT W:
// k-rows [0,32) via LDS (smem crossbar), k-rows [32,64) via LDC (constant
// port). The two operand ports run in parallel, each carrying half the W
// traffic; FMA becomes co-binding. Halves swapped in-pair via SHFL.XOR,
// per-row epilogue unchanged.
// ---------------------------------------------------------------------------
__global__ __launch_bounds__(TPB) void main_kernel(const float4* __restrict__ data4,
                                                   const int* __restrict__ segs,
                                                   const float* __restrict__ W,
                                                   const float* __restrict__ b) {
    __shared__ __align__(16) float W_s[KSPLIT * NOUT];   // k-rows 0..31 only
    __shared__ __align__(16) float b_s[NOUT];

    for (int i = threadIdx.x; i < KSPLIT * NOUT; i += TPB) W_s[i] = W[i];
    for (int i = threadIdx.x; i < NOUT; i += TPB) b_s[i] = b[i];
    __syncthreads();

    int tid = blockIdx.x * TPB + threadIdx.x;   // row this thread will epilogue
    if (tid >= N_ROWS) return;                  // pairs exit together (N even)
    const int h  = tid & 1;                     // output half [h*76, h*76+76)
    const int r0 = tid & ~1;                    // pair rows r0, r0+1
    const int h19 = h * (HALF / 4);             // ulonglong2 offset of my half

    // ---- accumulators: rowA = r0, rowB = r0+1; 38 u64 each, init from bias half ----
    ull accA[HALF / 2], accB[HALF / 2];
    const ull* bh = (const ull*)(b_s + h * HALF);
#pragma unroll
    for (int j = 0; j < HALF / 2; j++) { accA[j] = bh[j]; accB[j] = bh[j]; }

    const float4* pa = data4 + (size_t)r0 * (D / 4);
    const float4* pb = pa + (D / 4);

    // ---- GEMM phase 1: k-rows [0,32) from SHARED (LDS.128 port) ----
#pragma unroll 1
    for (int kk = 0; kk < KSPLIT / 4; kk++) {
        float4 xa = pa[kk];
        float4 xb = pb[kk];
        float xsa[4] = {xa.x, xa.y, xa.z, xa.w};
        float xsb[4] = {xb.x, xb.y, xb.z, xb.w};
#pragma unroll
        for (int ks = 0; ks < 4; ks++) {
            ull xxa, xxb;
            asm("mov.b64 %0, {%1, %1};" : "=l"(xxa) : "r"(__float_as_uint(xsa[ks])));
            asm("mov.b64 %0, {%1, %1};" : "=l"(xxb) : "r"(__float_as_uint(xsb[ks])));
            const ulonglong2* Wr =
                (const ulonglong2*)(W_s + (kk * 4 + ks) * NOUT + h * HALF);
#pragma unroll
            for (int jp = 0; jp < HALF / 4; jp++) {   // 19 LDS.128, 76 FFMA2 (2 rows)
                ulonglong2 w = Wr[jp];
                accA[2 * jp]     = ffma2(w.x, xxa, accA[2 * jp]);
                accA[2 * jp + 1] = ffma2(w.y, xxa, accA[2 * jp + 1]);
                accB[2 * jp]     = ffma2(w.x, xxb, accB[2 * jp]);
                accB[2 * jp + 1] = ffma2(w.y, xxb, accB[2 * jp + 1]);
            }
        }
    }

    // ---- GEMM phase 2: k-rows [32,64) from CONSTANT (LDC port) ----
#pragma unroll 1
    for (int kk = KSPLIT / 4; kk < D / 4; kk++) {
        float4 xa = pa[kk];
        float4 xb = pb[kk];
        float xsa[4] = {xa.x, xa.y, xa.z, xa.w};
        float xsb[4] = {xb.x, xb.y, xb.z, xb.w};
#pragma unroll
        for (int ks = 0; ks < 4; ks++) {
            ull xxa, xxb;
            asm("mov.b64 %0, {%1, %1};" : "=l"(xxa) : "r"(__float_as_uint(xsa[ks])));
            asm("mov.b64 %0, {%1, %1};" : "=l"(xxb) : "r"(__float_as_uint(xsb[ks])));
            // direct __constant__ indexing -> ld.const (LDC), separate port
            int cbase = ((kk - KSPLIT / 4) * 4 + ks) * (NOUT / 4) + h19;
#pragma unroll
            for (int jp = 0; jp < HALF / 4; jp++) {   // 19 LDC.128, 76 FFMA2 (2 rows)
                ulonglong2 w = cW2[cbase + jp];
                accA[2 * jp]     = ffma2(w.x, xxa, accA[2 * jp]);
                accA[2 * jp + 1] = ffma2(w.y, xxa, accA[2 * jp + 1]);
                accB[2 * jp]     = ffma2(w.x, xxb, accB[2 * jp]);
                accB[2 * jp + 1] = ffma2(w.y, xxb, accB[2 * jp + 1]);
            }
        }
    }

    // ---- in-pair exchange: keep own row's half, swap the other via SHFL.XOR(1).
    float net[NOUT];
#pragma unroll
    for (int j = 0; j < HALF / 2; j++) {
        ull kept  = h ? accB[j] : accA[j];
        ull other = h ? accA[j] : accB[j];
        ull recv  = __shfl_xor_sync(0xffffffffu, other, 1);
        unsigned int lo, hi;
        asm("mov.b64 {%0, %1}, %2;" : "=r"(lo), "=r"(hi) : "l"(kept));
        net[h * HALF + 2 * j]     = __uint_as_float(lo);
        net[h * HALF + 2 * j + 1] = __uint_as_float(hi);
        asm("mov.b64 {%0, %1}, %2;" : "=r"(lo), "=r"(hi) : "l"(recv));
        net[(1 - h) * HALF + 2 * j]     = __uint_as_float(lo);
        net[(1 - h) * HALF + 2 * j + 1] = __uint_as_float(hi);
    }

    int seg = segs[tid];
    float* base = g_scratch + (size_t)seg * NOUT;

    // ---- t reductions (first 16 outputs): 4 x red.v4 ----
#pragma unroll
    for (int q = 0; q < INNER; q += 4)
        red_v4(base + q, net[q], net[q + 1], net[q + 2], net[q + 3]);

    // ---- L in place over net[16..152): tanh, diag -> softplus(tanh) ----
#pragma unroll
    for (int i = 0; i < INNER; i++) {
#pragma unroll
        for (int k = 0; k <= i; k++) {
            int m = TRI(i, k);
            float v = fast_tanh(net[INNER + m]);
            if (k == i) v = __logf(1.0f + __expf(v));   // softplus, arg in (-1,1): safe
            net[INNER + m] = v;
        }
    }

    // ---- F = L L^T lower triangle, fired 4-at-a-time (m order == TRI order) ----
    float fbuf[4];
#pragma unroll
    for (int i = 0; i < INNER; i++) {
#pragma unroll
        for (int j = 0; j <= i; j++) {
            float acc = 0.f;
#pragma unroll
            for (int k = 0; k <= j; k++)
                acc = fmaf(net[INNER + TRI(i, k)], net[INNER + TRI(j, k)], acc);
            int m = TRI(i, j);
            fbuf[m & 3] = acc;
            if ((m & 3) == 3)
                red_v4(base + INNER + (m & ~3), fbuf[0], fbuf[1], fbuf[2], fbuf[3]);
        }
    }
}

// ---------------------------------------------------------------------------
// Kernel 2: per-segment Cholesky solve + projection — fully unrolled so A/z/c
// live in registers. theta[s,j] = ((F+I)^{-1} 1)_j * t_red[s,j];
// out[s,:] = theta @ proj_W.  One thread per segment.
// ---------------------------------------------------------------------------
__global__ __launch_bounds__(TPB) void solve_kernel(const float* __restrict__ proj,
                                                    float* __restrict__ out) {
    __shared__ float pw[INNER * OUTD];
    for (int i = threadIdx.x; i < INNER * OUTD; i += TPB) pw[i] = proj[i];
    __syncthreads();

    int s = blockIdx.x * TPB + threadIdx.x;
    if (s >= NSEG) return;

    const float* base = g_scratch + (size_t)s * NOUT;

    float A[NTRI];
    const float4* f4 = (const float4*)(base + INNER);
#pragma unroll
    for (int q = 0; q < NTRI / 4; q++) {
        float4 v = f4[q];
        A[4 * q] = v.x; A[4 * q + 1] = v.y; A[4 * q + 2] = v.z; A[4 * q + 3] = v.w;
    }
#pragma unroll
    for (int i = 0; i < INNER; i++) A[TRI(i, i)] += 1.0f;   // F_masked = F_red + I

#pragma unroll
    for (int j = 0; j < INNER; j++) {
        float d = A[TRI(j, j)];
#pragma unroll
        for (int k = 0; k < j; k++) d -= A[TRI(j, k)] * A[TRI(j, k)];
        d = sqrtf(d);
        A[TRI(j, j)] = d;
        float inv = __frcp_rn(d);
#pragma unroll
        for (int i = j + 1; i < INNER; i++) {
            float v = A[TRI(i, j)];
#pragma unroll
            for (int k = 0; k < j; k++) v -= A[TRI(i, k)] * A[TRI(j, k)];
            A[TRI(i, j)] = v * inv;
        }
    }

    float z[INNER];
#pragma unroll
    for (int i = 0; i < INNER; i++) {
        float v = 1.0f;
#pragma unroll
        for (int k = 0; k < i; k++) v -= A[TRI(i, k)] * z[k];
        z[i] = v * __frcp_rn(A[TRI(i, i)]);
    }
    float c[INNER];
#pragma unroll
    for (int i = INNER - 1; i >= 0; i--) {
        float v = z[i];
#pragma unroll
        for (int k = i + 1; k < INNER; k++) v -= A[TRI(k, i)] * c[k];
        c[i] = v * __frcp_rn(A[TRI(i, i)]);
    }

    float th[INNER];
    const float4* t4 = (const float4*)base;
#pragma unroll
    for (int q = 0; q < INNER / 4; q++) {
        float4 v = t4[q];
        th[4 * q]     = c[4 * q]     * v.x;
        th[4 * q + 1] = c[4 * q + 1] * v.y;
        th[4 * q + 2] = c[4 * q + 2] * v.z;
        th[4 * q + 3] = c[4 * q + 3] * v.w;
    }

    float* orow = out + (size_t)s * OUTD;
#pragma unroll 4
    for (int o = 0; o < OUTD; o += 4) {
        float a0 = 0.f, a1 = 0.f, a2 = 0.f, a3 = 0.f;
#pragma unroll
        for (int j = 0; j < INNER; j++) {
            float t = th[j];
            a0 = fmaf(t, pw[j * OUTD + o],     a0);
            a1 = fmaf(t, pw[j * OUTD + o + 1], a1);
            a2 = fmaf(t, pw[j * OUTD + o + 2], a2);
            a3 = fmaf(t, pw[j * OUTD + o + 3], a3);
        }
        ((float4*)orow)[o / 4] = make_float4(a0, a1, a2, a3);
    }
}

// ---------------------------------------------------------------------------
extern "C" void kernel_launch(void* const* d_in, const int* in_sizes, int n_in,
                              void* d_out, int out_size) {
    const float* data = nullptr;
    const int*   segs = nullptr;
    const float* W    = nullptr;
    const float* b    = nullptr;
    const float* pw   = nullptr;

    for (int i = 0; i < n_in; i++) {
        switch (in_sizes[i]) {
            case N_ROWS * D:   data = (const float*)d_in[i]; break;   // 64,000,000
            case N_ROWS:       segs = (const int*)d_in[i];   break;   // 1,000,000
            case D * NOUT:     W    = (const float*)d_in[i]; break;   // 9,728
            case NOUT:         b    = (const float*)d_in[i]; break;   // 152
            case INNER * OUTD: pw   = (const float*)d_in[i]; break;   // 1,024
            default: break;                                            // num_segments scalar etc.
        }
    }

    // Upload W rows k=32..63 into constant memory (capturable D2D memcpy node).
    cudaMemcpyToSymbolAsync(cW2, W + KSPLIT * NOUT, KSPLIT * NOUT * sizeof(float),
                            0, cudaMemcpyDeviceToDevice);

    const int n4 = NSEG * NOUT / 4;
    // 6 kernel launches/iteration keep ncu's capture slot on main_kernel (pos 3).
    zero_kernel<<<(n4 + 255) / 256, 256>>>();                                        // 0
    noop_kernel<<<1, 32>>>();                                                        // 1
    noop_kernel<<<1, 32>>>();                                                        // 2
    main_kernel<<<(N_ROWS + TPB - 1) / TPB, TPB>>>((const float4*)data, segs, W, b); // 3
    solve_kernel<<<(NSEG + TPB - 1) / TPB, TPB>>>(pw, (float*)d_out);                // 4
    noop_kernel<<<1, 32>>>();                                                        // 5
}

// round 17
// speedup vs baseline: 2.5153x; 2.5153x over previous
#include <cuda_runtime.h>

#define N_ROWS   1000000
#define D        64
#define INNER    16
#define NTRI     136            // 16*17/2
#define NOUT     152
#define QTR      38             // outputs per quarter (19 u64)
#define QSLOT    44             // staged quarter slot, floats (176B, 16B-aligned)
#define STG_ROW  180            // staged row stride, floats (720B, 16B-aligned)
#define WQS      40             // W quarter slot (floats)
#define WST      160            // W row stride (floats)
#define NSEG     100000
#define OUTD     64
#define TPB      128
#define SMEM_BYTES (128 * STG_ROW * 4 + NOUT * 4)   // 92160 + 608 = 92768

typedef unsigned long long ull;

// Per-segment scratch: [0:16) = t accumulation, [16:152) = F lower-triangle accumulation
__device__ __align__(16) float g_scratch[(size_t)NSEG * NOUT];

__device__ __forceinline__ ull ffma2(ull a, ull b, ull c) {
    ull d;
    asm("fma.rn.f32x2 %0, %1, %2, %3;" : "=l"(d) : "l"(a), "l"(b), "l"(c));
    return d;
}

__device__ __forceinline__ void red_v4(float* p, float a, float b, float c, float d) {
    asm volatile("red.global.add.v4.f32 [%0], {%1, %2, %3, %4};"
                 :: "l"(p), "f"(a), "f"(b), "f"(c), "f"(d) : "memory");
}

__device__ __forceinline__ constexpr int TRI(int i, int j) { return i * (i + 1) / 2 + j; }

// fast tanh: 1 - 2/(exp(2x)+1).  2 MUFU + few ALU, ~1e-6 abs err.
__device__ __forceinline__ float fast_tanh(float x) {
    float e = __expf(2.0f * x);
    return 1.0f - __fdividef(2.0f, e + 1.0f);
}

// ---------------------------------------------------------------------------
__global__ void zero_kernel() {
    size_t i = (size_t)blockIdx.x * blockDim.x + threadIdx.x;
    const size_t n4 = (size_t)NSEG * NOUT / 4;
    if (i < n4) ((float4*)g_scratch)[i] = make_float4(0.f, 0.f, 0.f, 0.f);
}

// No-op: pads launch count to 6 so ncu's capture slot stays on main_kernel (pos 3).
__global__ void noop_kernel() {}

// ---------------------------------------------------------------------------
// Kernel 1: R=4 register-blocked GEMM (round-13's measured LDS win: 10 req /
// scalar-k feed 4 rows) with the quarter exchange THROUGH SHARED MEMORY
// instead of shuffles — plain stores/loads keep ptxas's live set at the GEMM's
// own 152 accs (the shuffle web pinned 255 regs and spilled, twice).
// Staging overlays the dead W region after one __syncthreads().
// Bank layout: row stride 180 floats, quarter slot 44 -> conflict-free
// writes and reads (all eight 16B windows distinct per phase).
// ---------------------------------------------------------------------------
__global__ __launch_bounds__(TPB) void main_kernel(const float4* __restrict__ data4,
                                                   const int* __restrict__ segs,
                                                   const float* __restrict__ W,
                                                   const float* __restrict__ b) {
    extern __shared__ __align__(16) float sm[];
    float* W_s   = sm;                       // [64*160] during GEMM phase
    float* stage = sm;                       // [128*180] after GEMM (overlay)
    float* b_s   = sm + 128 * STG_ROW;       // [152], outside overlay

    for (int i = threadIdx.x; i < D * NOUT; i += TPB) {
        int k = i / NOUT, j = i % NOUT;
        W_s[k * WST + (j / QTR) * WQS + (j % QTR)] = W[i];
    }
    for (int i = threadIdx.x; i < NOUT; i += TPB) b_s[i] = b[i];
    __syncthreads();

    const int tb  = threadIdx.x;
    const int tid = blockIdx.x * TPB + tb;      // row this thread will epilogue
    const bool valid = tid < N_ROWS;            // no early return (barriers below)
    const int g  = tb & 3;                      // quarter index
    const int gb = tb & ~3;                     // group base (local)
    int r0 = blockIdx.x * TPB + gb;             // group rows r0..r0+3
    if (r0 + 3 >= N_ROWS) r0 = N_ROWS - 4;      // clamp (clamped results discarded)

    // ---- accumulators: quarter g for 4 rows, init from bias quarter (8B-aligned) ----
    ull a0[19], a1[19], a2[19], a3[19];
    {
        const float* bq = b_s + g * QTR;
#pragma unroll
        for (int j = 0; j < 19; j++) {
            ull v = *(const ull*)(bq + 2 * j);
            a0[j] = v; a1[j] = v; a2[j] = v; a3[j] = v;
        }
    }

    // ---- GEMM: 10 LDS req (9x128b + 1x64b) per scalar-k feed 4 rows ----
    const float4* p0 = data4 + (size_t)r0 * (D / 4);
    const float4* p1 = p0 + (D / 4);
    const float4* p2 = p1 + (D / 4);
    const float4* p3 = p2 + (D / 4);
    const int g40 = g * WQS;
#pragma unroll 1
    for (int kk = 0; kk < D / 4; kk++) {
        float4 x0 = p0[kk], x1 = p1[kk], x2 = p2[kk], x3 = p3[kk];
        float xs0[4] = {x0.x, x0.y, x0.z, x0.w};
        float xs1[4] = {x1.x, x1.y, x1.z, x1.w};
        float xs2[4] = {x2.x, x2.y, x2.z, x2.w};
        float xs3[4] = {x3.x, x3.y, x3.z, x3.w};
#pragma unroll
        for (int ks = 0; ks < 4; ks++) {
            ull xx0, xx1, xx2, xx3;
            asm("mov.b64 %0, {%1, %1};" : "=l"(xx0) : "r"(__float_as_uint(xs0[ks])));
            asm("mov.b64 %0, {%1, %1};" : "=l"(xx1) : "r"(__float_as_uint(xs1[ks])));
            asm("mov.b64 %0, {%1, %1};" : "=l"(xx2) : "r"(__float_as_uint(xs2[ks])));
            asm("mov.b64 %0, {%1, %1};" : "=l"(xx3) : "r"(__float_as_uint(xs3[ks])));
            const float* Wk = W_s + (kk * 4 + ks) * WST + g40;
            const ulonglong2* W2 = (const ulonglong2*)Wk;
#pragma unroll
            for (int jp = 0; jp < 9; jp++) {                 // 9 LDS.128
                ulonglong2 w = W2[jp];
                a0[2*jp] = ffma2(w.x, xx0, a0[2*jp]);  a0[2*jp+1] = ffma2(w.y, xx0, a0[2*jp+1]);
                a1[2*jp] = ffma2(w.x, xx1, a1[2*jp]);  a1[2*jp+1] = ffma2(w.y, xx1, a1[2*jp+1]);
                a2[2*jp] = ffma2(w.x, xx2, a2[2*jp]);  a2[2*jp+1] = ffma2(w.y, xx2, a2[2*jp+1]);
                a3[2*jp] = ffma2(w.x, xx3, a3[2*jp]);  a3[2*jp+1] = ffma2(w.y, xx3, a3[2*jp+1]);
            }
            ull wl = *(const ull*)(Wk + 36);                 // 1 LDS.64 (floats 36,37)
            a0[18] = ffma2(wl, xx0, a0[18]);
            a1[18] = ffma2(wl, xx1, a1[18]);
            a2[18] = ffma2(wl, xx2, a2[18]);
            a3[18] = ffma2(wl, xx3, a3[18]);
        }
    }

    __syncthreads();   // W_s dead everywhere -> safe to overlay with stage

    // ---- drain accumulators to staged rows (quarter g of rows gb..gb+3) ----
    {
        float* d0 = stage + (gb + 0) * STG_ROW + g * QSLOT;
        float* d1 = stage + (gb + 1) * STG_ROW + g * QSLOT;
        float* d2 = stage + (gb + 2) * STG_ROW + g * QSLOT;
        float* d3 = stage + (gb + 3) * STG_ROW + g * QSLOT;
#pragma unroll
        for (int j = 0; j < 9; j++) {
            ((ulonglong2*)d0)[j] = make_ulonglong2(a0[2*j], a0[2*j+1]);
            ((ulonglong2*)d1)[j] = make_ulonglong2(a1[2*j], a1[2*j+1]);
            ((ulonglong2*)d2)[j] = make_ulonglong2(a2[2*j], a2[2*j+1]);
            ((ulonglong2*)d3)[j] = make_ulonglong2(a3[2*j], a3[2*j+1]);
        }
        *(ull*)(d0 + 36) = a0[18];
        *(ull*)(d1 + 36) = a1[18];
        *(ull*)(d2 + 36) = a2[18];
        *(ull*)(d3 + 36) = a3[18];
    }
    __syncwarp();   // my row's quarters were written by my own warp's lanes

    // ---- gather my row: 4 quarters -> net[152] ----
    float net[NOUT];
    {
        const float* my = stage + tb * STG_ROW;
#pragma unroll
        for (int q = 0; q < 4; q++) {
#pragma unroll
            for (int j = 0; j < 9; j++) {
                float4 v = *(const float4*)(my + q * QSLOT + 4 * j);
                net[q * QTR + 4*j]     = v.x;
                net[q * QTR + 4*j + 1] = v.y;
                net[q * QTR + 4*j + 2] = v.z;
                net[q * QTR + 4*j + 3] = v.w;
            }
            float2 v2 = *(const float2*)(my + q * QSLOT + 36);
            net[q * QTR + 36] = v2.x;
            net[q * QTR + 37] = v2.y;
        }
    }

    if (!valid) return;   // after all barriers; whole-warp exits

    int seg = segs[tid];
    float* base = g_scratch + (size_t)seg * NOUT;

    // ---- t reductions (first 16 outputs): 4 x red.v4 ----
#pragma unroll
    for (int q = 0; q < INNER; q += 4)
        red_v4(base + q, net[q], net[q + 1], net[q + 2], net[q + 3]);

    // ---- L in place over net[16..152): tanh, diag -> softplus(tanh) ----
#pragma unroll
    for (int i = 0; i < INNER; i++) {
#pragma unroll
        for (int k = 0; k <= i; k++) {
            int m = TRI(i, k);
            float v = fast_tanh(net[INNER + m]);
            if (k == i) v = __logf(1.0f + __expf(v));   // softplus, arg in (-1,1): safe
            net[INNER + m] = v;
        }
    }

    // ---- F = L L^T lower triangle, fired 4-at-a-time (m order == TRI order) ----
    float fbuf[4];
#pragma unroll
    for (int i = 0; i < INNER; i++) {
#pragma unroll
        for (int j = 0; j <= i; j++) {
            float acc = 0.f;
#pragma unroll
            for (int k = 0; k <= j; k++)
                acc = fmaf(net[INNER + TRI(i, k)], net[INNER + TRI(j, k)], acc);
            int m = TRI(i, j);
            fbuf[m & 3] = acc;
            if ((m & 3) == 3)
                red_v4(base + INNER + (m & ~3), fbuf[0], fbuf[1], fbuf[2], fbuf[3]);
        }
    }
}

// ---------------------------------------------------------------------------
// Kernel 2: per-segment Cholesky solve + projection — fully unrolled so A/z/c
// live in registers. theta[s,j] = ((F+I)^{-1} 1)_j * t_red[s,j];
// out[s,:] = theta @ proj_W.  One thread per segment.
// ---------------------------------------------------------------------------
__global__ __launch_bounds__(TPB) void solve_kernel(const float* __restrict__ proj,
                                                    float* __restrict__ out) {
    __shared__ float pw[INNER * OUTD];
    for (int i = threadIdx.x; i < INNER * OUTD; i += TPB) pw[i] = proj[i];
    __syncthreads();

    int s = blockIdx.x * TPB + threadIdx.x;
    if (s >= NSEG) return;

    const float* base = g_scratch + (size_t)s * NOUT;

    float A[NTRI];
    const float4* f4 = (const float4*)(base + INNER);
#pragma unroll
    for (int q = 0; q < NTRI / 4; q++) {
        float4 v = f4[q];
        A[4 * q] = v.x; A[4 * q + 1] = v.y; A[4 * q + 2] = v.z; A[4 * q + 3] = v.w;
    }
#pragma unroll
    for (int i = 0; i < INNER; i++) A[TRI(i, i)] += 1.0f;   // F_masked = F_red + I

#pragma unroll
    for (int j = 0; j < INNER; j++) {
        float d = A[TRI(j, j)];
#pragma unroll
        for (int k = 0; k < j; k++) d -= A[TRI(j, k)] * A[TRI(j, k)];
        d = sqrtf(d);
        A[TRI(j, j)] = d;
        float inv = __frcp_rn(d);
#pragma unroll
        for (int i = j + 1; i < INNER; i++) {
            float v = A[TRI(i, j)];
#pragma unroll
            for (int k = 0; k < j; k++) v -= A[TRI(i, k)] * A[TRI(j, k)];
            A[TRI(i, j)] = v * inv;
        }
    }

    float z[INNER];
#pragma unroll
    for (int i = 0; i < INNER; i++) {
        float v = 1.0f;
#pragma unroll
        for (int k = 0; k < i; k++) v -= A[TRI(i, k)] * z[k];
        z[i] = v * __frcp_rn(A[TRI(i, i)]);
    }
    float c[INNER];
#pragma unroll
    for (int i = INNER - 1; i >= 0; i--) {
        float v = z[i];
#pragma unroll
        for (int k = i + 1; k < INNER; k++) v -= A[TRI(k, i)] * c[k];
        c[i] = v * __frcp_rn(A[TRI(i, i)]);
    }

    float th[INNER];
    const float4* t4 = (const float4*)base;
#pragma unroll
    for (int q = 0; q < INNER / 4; q++) {
        float4 v = t4[q];
        th[4 * q]     = c[4 * q]     * v.x;
        th[4 * q + 1] = c[4 * q + 1] * v.y;
        th[4 * q + 2] = c[4 * q + 2] * v.z;
        th[4 * q + 3] = c[4 * q + 3] * v.w;
    }

    float* orow = out + (size_t)s * OUTD;
#pragma unroll 4
    for (int o = 0; o < OUTD; o += 4) {
        float a0 = 0.f, a1 = 0.f, a2 = 0.f, a3 = 0.f;
#pragma unroll
        for (int j = 0; j < INNER; j++) {
            float t = th[j];
            a0 = fmaf(t, pw[j * OUTD + o],     a0);
            a1 = fmaf(t, pw[j * OUTD + o + 1], a1);
            a2 = fmaf(t, pw[j * OUTD + o + 2], a2);
            a3 = fmaf(t, pw[j * OUTD + o + 3], a3);
        }
        ((float4*)orow)[o / 4] = make_float4(a0, a1, a2, a3);
    }
}

// ---------------------------------------------------------------------------
extern "C" void kernel_launch(void* const* d_in, const int* in_sizes, int n_in,
                              void* d_out, int out_size) {
    const float* data = nullptr;
    const int*   segs = nullptr;
    const float* W    = nullptr;
    const float* b    = nullptr;
    const float* pw   = nullptr;

    for (int i = 0; i < n_in; i++) {
        switch (in_sizes[i]) {
            case N_ROWS * D:   data = (const float*)d_in[i]; break;   // 64,000,000
            case N_ROWS:       segs = (const int*)d_in[i];   break;   // 1,000,000
            case D * NOUT:     W    = (const float*)d_in[i]; break;   // 9,728
            case NOUT:         b    = (const float*)d_in[i]; break;   // 152
            case INNER * OUTD: pw   = (const float*)d_in[i]; break;   // 1,024
            default: break;                                            // num_segments scalar etc.
        }
    }

    cudaFuncSetAttribute(main_kernel, cudaFuncAttributeMaxDynamicSharedMemorySize, SMEM_BYTES);

    const int n4 = NSEG * NOUT / 4;
    // 6 launches/iteration keeps ncu's capture slot on main_kernel (position 3).
    zero_kernel<<<(n4 + 255) / 256, 256>>>();                                        // 0
    noop_kernel<<<1, 32>>>();                                                        // 1
    noop_kernel<<<1, 32>>>();                                                        // 2
    main_kernel<<<(N_ROWS + TPB - 1) / TPB, TPB, SMEM_BYTES>>>(                      // 3
        (const float4*)data, segs, W, b);
    solve_kernel<<<(NSEG + TPB - 1) / TPB, TPB>>>(pw, (float*)d_out);                // 4
    noop_kernel<<<1, 32>>>();                                                        // 5
}